// round 11
// baseline (speedup 1.0000x reference)
#include <cuda_runtime.h>
#include <cuda_bf16.h>

typedef unsigned long long u64t;

__device__ __forceinline__ void ffma2(u64t& d, u64t a, u64t b) {
    asm("fma.rn.f32x2 %0, %1, %2, %0;" : "+l"(d) : "l"(a), "l"(b));
}
__device__ __forceinline__ u64t packdup(float v) {
    u64t r;
    asm("mov.b64 %0, {%1, %1};" : "=l"(r) : "r"(__float_as_uint(v)));
    return r;
}
__device__ __forceinline__ u64t pack2(float a, float b) {
    u64t r;
    asm("mov.b64 %0, {%1, %2};" : "=l"(r) : "r"(__float_as_uint(a)), "r"(__float_as_uint(b)));
    return r;
}
__device__ __forceinline__ float2 unpk(u64t p) {
    unsigned lo, hi;
    asm("mov.b64 {%0, %1}, %2;" : "=r"(lo), "=r"(hi) : "l"(p));
    return make_float2(__uint_as_float(lo), __uint_as_float(hi));
}
__device__ __forceinline__ void cp_async4(void* smem, const void* gmem) {
    unsigned s = (unsigned)__cvta_generic_to_shared(smem);
    asm volatile("cp.async.ca.shared.global [%0], [%1], 4;" :: "r"(s), "l"(gmem));
}
__device__ __forceinline__ void cp_commit() {
    asm volatile("cp.async.commit_group;" ::: "memory");
}
template <int N>
__device__ __forceinline__ void cp_wait() {
    asm volatile("cp.async.wait_group %0;" :: "n"(N) : "memory");
}

__device__ float g_encb1[16 * 128 * 128 * 128];
__device__ float g_encb [16 * 128 * 64 * 64];
__device__ float g_enct [2 * 16 * 128 * 32 * 32];   // split-K partials for conv3
__device__ float g_dect [16 * 64 * 64 * 64];
__device__ float g_upt  [16 * 64 * 64 * 64];
__device__ float g_h    [16 * 64 * 128 * 128];
__device__ float g_normt[512];
__device__ float g_normb[512];
__device__ float g_acc[2];

__global__ void init_kernel(const float* __restrict__ et, const float* __restrict__ eb,
                            float* __restrict__ nt, float* __restrict__ nb,
                            float* __restrict__ acc) {
    int k = threadIdx.x; // 512 threads
    float st = 0.f, sb = 0.f;
#pragma unroll
    for (int d = 0; d < 64; d++) {
        float a = et[d * 512 + k]; st = fmaf(a, a, st);
        float b = eb[d * 512 + k]; sb = fmaf(b, b, sb);
    }
    nt[k] = st;
    nb[k] = sb;
    if (k < 2) acc[k] = 0.f;
}

// ---------------------------------------------------------------------------
// 4x4 stride-2 pad-1 conv (+relu). 128 threads = 4 lane4 x 4 sx x 8 sy.
// Each thread: 2x4 output pixels x 8 couts. Output tile 16x16.
// Input smem DUPLICATED: [v,v] pairs -> broadcast operand via one LDS.64.
// Per (c,kk): 8 LDS.64 + 2 LDS.128 -> 32 FFMA2 (no MOVs).
// ---------------------------------------------------------------------------
#define CCHNK 2
template <bool RELU, int KS>
__global__ __launch_bounds__(128, 4) void conv4x4s2_kernel(
    const float* __restrict__ in, const float* __restrict__ w,
    const float* __restrict__ bias, float* __restrict__ out,
    int N, int Cin, int Cout, int Hin, int Win) {
    const int Hout = Hin >> 1, Wout = Win >> 1;
    const int tid = threadIdx.x;
    const int lane4 = tid & 3;
    const int sp = tid >> 2;             // 0..31
    const int sx = sp & 3, sy = sp >> 2; // sx 0..3, sy 0..7
    const int ox0 = blockIdx.x << 4, oy0 = blockIdx.y << 4;
    const int cog = Cout >> 5;
    const int zdiv = cog * KS;
    const int n = blockIdx.z / zdiv;
    const int rem = blockIdx.z % zdiv;
    const int ks = rem / cog;
    const int co0 = (rem % cog) << 5;
    const int CinL = Cin / KS;
    const int ciBase = ks * CinL;
    float* outp = out + (size_t)ks * N * Cout * Hout * Wout;

    __shared__ float s_in[2][CCHNK][34][34][2]; // duplicated pairs
    __shared__ float s_w[2][CCHNK][16][36];

    u64t acc2[8][4];
#pragma unroll
    for (int p = 0; p < 8; p++)
#pragma unroll
        for (int j = 0; j < 4; j++) acc2[p][j] = 0ull;

    const int iyb = 2 * oy0 - 1, ixb = 2 * ox0 - 1;
    const int by = 4 * sy, bx = 8 * sx;

    for (int idx = tid; idx < 2 * CCHNK * 1156 * 2; idx += 128)
        ((float*)s_in)[idx] = 0.f;
    __syncthreads();

    auto load_chunk = [&](int ci0, int buf) {
        const int cc = min(CCHNK, CinL - ci0);
        for (int idx = tid; idx < cc * 1156; idx += 128) {
            int c = idx / 1156, r = idx - c * 1156;
            int yy = r / 34, xx = r - yy * 34;
            int iy = iyb + yy, ix = ixb + xx;
            if ((unsigned)iy < (unsigned)Hin && (unsigned)ix < (unsigned)Win) {
                const float* src = &in[((n * Cin + ciBase + ci0 + c) * Hin + iy) * Win + ix];
                cp_async4(&s_in[buf][c][yy][xx][0], src);
                cp_async4(&s_in[buf][c][yy][xx][1], src);
            }
        }
        const int cseg = cc * 16;
        for (int idx = tid; idx < cc * 512; idx += 128) {
            int co = idx / cseg;
            int r = idx - co * cseg;
            int c = r >> 4, kk = r & 15;
            cp_async4(&s_w[buf][c][kk][co],
                      &w[(co0 + co) * Cin * 16 + (ciBase + ci0) * 16 + r]);
        }
        cp_commit();
    };

    const int nch = (CinL + CCHNK - 1) / CCHNK;
    load_chunk(0, 0);
    for (int it = 0; it < nch; it++) {
        const int buf = it & 1;
        if (it + 1 < nch) { load_chunk((it + 1) * CCHNK, buf ^ 1); cp_wait<1>(); }
        else cp_wait<0>();
        __syncthreads();
        const int cc = min(CCHNK, CinL - it * CCHNK);
        for (int c = 0; c < cc; c++) {
#pragma unroll
            for (int kk = 0; kk < 16; kk++) {
                const int ky = kk >> 2, kx = kk & 3;
                u64t vp[8];
#pragma unroll
                for (int dy = 0; dy < 2; dy++)
#pragma unroll
                    for (int dx = 0; dx < 4; dx++)
                        vp[dy * 4 + dx] = *(const u64t*)&s_in[buf][c][by + 2 * dy + ky][bx + 2 * dx + kx][0];
                const float* wp = &s_w[buf][c][kk][lane4 * 8];
                const ulonglong2 wA = *(const ulonglong2*)(wp);
                const ulonglong2 wB = *(const ulonglong2*)(wp + 4);
                const u64t wv[4] = {wA.x, wA.y, wB.x, wB.y};
#pragma unroll
                for (int j = 0; j < 4; j++)
#pragma unroll
                    for (int p = 0; p < 8; p++)
                        ffma2(acc2[p][j], vp[p], wv[j]);
            }
        }
        __syncthreads();
    }
#pragma unroll
    for (int dy = 0; dy < 2; dy++)
#pragma unroll
        for (int dx = 0; dx < 4; dx++) {
            const int oy = oy0 + 2 * sy + dy, ox = ox0 + 4 * sx + dx;
#pragma unroll
            for (int j = 0; j < 4; j++) {
                const int co = co0 + lane4 * 8 + 2 * j;
                const float2 pv = unpk(acc2[dy * 4 + dx][j]);
                float r0 = pv.x, r1 = pv.y;
                if (KS == 1) { r0 += bias[co]; r1 += bias[co + 1]; }
                if (RELU) { r0 = fmaxf(r0, 0.f); r1 = fmaxf(r1, 0.f); }
                outp[((n * Cout + co) * Hout + oy) * Wout + ox] = r0;
                outp[((n * Cout + co + 1) * Hout + oy) * Wout + ox] = r1;
            }
        }
}

// ---------------------------------------------------------------------------
// convT. 128 threads; 2x4 output pixels x 8 couts; duplicated-input smem.
// DUAL: dect+upt fusion (two weight/output sets share input tile).
// ---------------------------------------------------------------------------
#define TCHNK 8
template <bool RELU, bool DUAL>
__global__ __launch_bounds__(128, 4) void convT4x4_kernel(
    const float* __restrict__ inA, const float* __restrict__ inB, int CA,
    const float* __restrict__ w, const float* __restrict__ bias,
    float* __restrict__ out,
    const float* __restrict__ w2, const float* __restrict__ bias2,
    float* __restrict__ out2,
    int N, int Cin, int Cout, int Hin, int Win) {
    const int Hout = Hin << 1, Wout = Win << 1;
    const int tid = threadIdx.x;
    const int lane4 = tid & 3;
    const int sp = tid >> 2;
    const int sx = sp & 3, sy = sp >> 2; // sx 0..3, sy 0..7
    const int ox0 = blockIdx.x << 4, oy0 = blockIdx.y << 4;
    const int cog = Cout >> 5;
    const int zdiv = cog * (DUAL ? 2 : 1);
    const int n = blockIdx.z / zdiv;
    int g = blockIdx.z % zdiv;
    const float* wU = w;
    const float* bU = bias;
    float* oU = out;
    if (DUAL && g >= cog) { wU = w2; bU = bias2; oU = out2; g -= cog; }
    const int co0 = g << 5;
    const int CB = Cin - CA;

    __shared__ float s_in[2][TCHNK][10][10][2]; // duplicated pairs
    __shared__ float s_w[2][TCHNK][16][36];

    u64t acc2[8][4];
#pragma unroll
    for (int p = 0; p < 8; p++)
#pragma unroll
        for (int j = 0; j < 4; j++) acc2[p][j] = 0ull;

    const int iy0 = (oy0 >> 1) - 1, ix0 = (ox0 >> 1) - 1;

    for (int idx = tid; idx < 2 * TCHNK * 100 * 2; idx += 128)
        ((float*)s_in)[idx] = 0.f;
    __syncthreads();

    auto load_chunk = [&](int ci0, int buf) {
        const int cc = min(TCHNK, Cin - ci0);
        for (int idx = tid; idx < cc * 100; idx += 128) {
            int c = idx / 100, r = idx - c * 100;
            int yy = r / 10, xx = r - yy * 10;
            int iy = iy0 + yy, ix = ix0 + xx;
            int ci = ci0 + c;
            if ((unsigned)iy < (unsigned)Hin && (unsigned)ix < (unsigned)Win) {
                const float* src = (ci < CA)
                    ? &inA[((n * CA + ci) * Hin + iy) * Win + ix]
                    : &inB[((n * CB + (ci - CA)) * Hin + iy) * Win + ix];
                cp_async4(&s_in[buf][c][yy][xx][0], src);
                cp_async4(&s_in[buf][c][yy][xx][1], src);
            }
        }
        for (int idx = tid; idx < cc * 512; idx += 128) {
            int c = idx >> 9, r = idx & 511; // r = co*16 + kk
            int co = r >> 4, kk = r & 15;
            cp_async4(&s_w[buf][c][kk][co], &wU[(ci0 + c) * Cout * 16 + co0 * 16 + r]);
        }
        cp_commit();
    };

    const int nch = (Cin + TCHNK - 1) / TCHNK;
    load_chunk(0, 0);
    for (int it = 0; it < nch; it++) {
        const int buf = it & 1;
        if (it + 1 < nch) { load_chunk((it + 1) * TCHNK, buf ^ 1); cp_wait<1>(); }
        else cp_wait<0>();
        __syncthreads();
        const int cc = min(TCHNK, Cin - it * TCHNK);
        for (int c = 0; c < cc; c++) {
            // register tile: rows sy..sy+2, cols 2sx..2sx+3 (as [v,v] pairs)
            u64t vin[3][4];
#pragma unroll
            for (int i = 0; i < 3; i++)
#pragma unroll
                for (int j2 = 0; j2 < 4; j2++)
                    vin[i][j2] = *(const u64t*)&s_in[buf][c][sy + i][2 * sx + j2][0];
#pragma unroll
            for (int kk = 0; kk < 16; kk++) {
                const int ky = kk >> 2, kx = kk & 3;
                const int dy = (ky & 1) ? 0 : 1;
                const int ry = (ky & 1) ? (1 - ((ky - 1) >> 1)) : (2 - (ky >> 1));
                const int dxx0 = (kx & 1) ? 0 : 1;          // first matching out-col offset
                const int c0 = ((dxx0 + 1 - kx) >> 1) + 1;  // vin col for dxx0 (0..2)
                const u64t va = vin[ry][c0];
                const u64t vb = vin[ry][c0 + 1];            // for dxx0 + 2
                const float* wp = &s_w[buf][c][kk][lane4 * 8];
                const ulonglong2 wA = *(const ulonglong2*)(wp);
                const ulonglong2 wB = *(const ulonglong2*)(wp + 4);
                const u64t wv[4] = {wA.x, wA.y, wB.x, wB.y};
                u64t* aa = acc2[dy * 4 + dxx0];
                u64t* ab = acc2[dy * 4 + dxx0 + 2];
#pragma unroll
                for (int j = 0; j < 4; j++) {
                    ffma2(aa[j], va, wv[j]);
                    ffma2(ab[j], vb, wv[j]);
                }
            }
        }
        __syncthreads();
    }
#pragma unroll
    for (int dy = 0; dy < 2; dy++)
#pragma unroll
        for (int dx = 0; dx < 4; dx++) {
            const int oy = oy0 + 2 * sy + dy, ox = ox0 + 4 * sx + dx;
#pragma unroll
            for (int j = 0; j < 4; j++) {
                const int co = co0 + lane4 * 8 + 2 * j;
                const float2 pv = unpk(acc2[dy * 4 + dx][j]);
                float r0 = pv.x + bU[co];
                float r1 = pv.y + bU[co + 1];
                if (RELU) { r0 = fmaxf(r0, 0.f); r1 = fmaxf(r1, 0.f); }
                oU[((n * Cout + co) * Hout + oy) * Wout + ox] = r0;
                oU[((n * Cout + co + 1) * Hout + oy) * Wout + ox] = r1;
            }
        }
}

// ---------------------------------------------------------------------------
// ConvT small (Cout=3), cp.async double-buffered (proven version)
// ---------------------------------------------------------------------------
#define SCHNK 8
__global__ __launch_bounds__(256) void convT4x4_small_kernel(
    const float* __restrict__ in, const float* __restrict__ w,
    const float* __restrict__ bias, float* __restrict__ out,
    int N, int Cin, int Hin, int Win) {
    const int Hout = Hin << 1, Wout = Win << 1;
    const int tid = threadIdx.x;
    const int sx = tid & 15, sy = tid >> 4;
    const int ox0 = blockIdx.x << 5, oy0 = blockIdx.y << 5;
    const int n = blockIdx.z;

    __shared__ float s_in[2][SCHNK][18][18];
    __shared__ float s_w[2][SCHNK][16][4];

    u64t acc01[4];
    float acc2s[4];
#pragma unroll
    for (int p = 0; p < 4; p++) { acc01[p] = 0ull; acc2s[p] = 0.f; }

    const int iy0 = (oy0 >> 1) - 1, ix0 = (ox0 >> 1) - 1;

    for (int idx = tid; idx < 2 * SCHNK * 324; idx += 256)
        ((float*)s_in)[idx] = 0.f;
    __syncthreads();

    auto load_chunk = [&](int ci0, int buf) {
        const int cc = min(SCHNK, Cin - ci0);
        for (int idx = tid; idx < cc * 324; idx += 256) {
            int c = idx / 324, r = idx - c * 324;
            int yy = r / 18, xx = r - yy * 18;
            int iy = iy0 + yy, ix = ix0 + xx;
            if ((unsigned)iy < (unsigned)Hin && (unsigned)ix < (unsigned)Win)
                cp_async4(&s_in[buf][c][yy][xx],
                          &in[((n * Cin + ci0 + c) * Hin + iy) * Win + ix]);
        }
        for (int idx = tid; idx < cc * 48; idx += 256) {
            int c = idx / 48, r = idx - c * 48;
            int co = r >> 4, kk = r & 15;
            cp_async4(&s_w[buf][c][kk][co], &w[(ci0 + c) * 3 * 16 + r]);
        }
        cp_commit();
    };

    const int nch = (Cin + SCHNK - 1) / SCHNK;
    load_chunk(0, 0);
    for (int it = 0; it < nch; it++) {
        const int buf = it & 1;
        if (it + 1 < nch) { load_chunk((it + 1) * SCHNK, buf ^ 1); cp_wait<1>(); }
        else cp_wait<0>();
        __syncthreads();
        const int cc = min(SCHNK, Cin - it * SCHNK);
        for (int c = 0; c < cc; c++) {
            float vin[3][3];
#pragma unroll
            for (int i = 0; i < 3; i++)
#pragma unroll
                for (int j2 = 0; j2 < 3; j2++) vin[i][j2] = s_in[buf][c][sy + i][sx + j2];
#pragma unroll
            for (int kk = 0; kk < 16; kk++) {
                const int ky = kk >> 2, kx = kk & 3;
                const int dy = (ky & 1) ? 0 : 1;
                const int ry = (ky & 1) ? (1 - ((ky - 1) >> 1)) : (2 - (ky >> 1));
                const int dx = (kx & 1) ? 0 : 1;
                const int rx = (kx & 1) ? (1 - ((kx - 1) >> 1)) : (2 - (kx >> 1));
                const float vs = vin[ry][rx];
                const u64t v = packdup(vs);
                const u64t w01 = *(const u64t*)&s_w[buf][c][kk][0];
                const int p = dy * 2 + dx;
                ffma2(acc01[p], v, w01);
                acc2s[p] = fmaf(vs, s_w[buf][c][kk][2], acc2s[p]);
            }
        }
        __syncthreads();
    }
#pragma unroll
    for (int dy = 0; dy < 2; dy++)
#pragma unroll
        for (int dx = 0; dx < 2; dx++) {
            const int oy = oy0 + 2 * sy + dy, ox = ox0 + 2 * sx + dx;
            const float2 pv = unpk(acc01[dy * 2 + dx]);
            out[((n * 3 + 0) * Hout + oy) * Wout + ox] = pv.x + bias[0];
            out[((n * 3 + 1) * Hout + oy) * Wout + ox] = pv.y + bias[1];
            out[((n * 3 + 2) * Hout + oy) * Wout + ox] = acc2s[dy * 2 + dx] + bias[2];
        }
}

// ---------------------------------------------------------------------------
// Fused 1x1 conv + VQ. 128 threads/block, 64-wide codebook chunks.
// MODE 0: concat input. MODE 1: relu(inA+inB+cbias) split-K input.
// ---------------------------------------------------------------------------
template <int MODE>
__global__ __launch_bounds__(128) void conv1x1_quantize_kernel(
    const float* __restrict__ inA, const float* __restrict__ inB, int CA, int CB,
    const float* __restrict__ cbias,
    const float* __restrict__ w, const float* __restrict__ b,
    const float* __restrict__ embed, const float* __restrict__ norms,
    float* __restrict__ qout, float* __restrict__ idout, float* __restrict__ acc,
    int HW) {
    const int tid = threadIdx.x;
    const int v = blockIdx.x * 128 + tid;
    const int n = v / HW, hw = v - n * HW;
    const int Cin = (MODE == 0) ? (CA + CB) : CA;

    __shared__ float s_w[2][16][68];
    __shared__ float s_e[2][64][68];
    __shared__ float s_n[2][64];

    u64t f2[32];
#pragma unroll
    for (int i = 0; i < 32; i++) f2[i] = 0ull;

    auto load_w = [&](int ci0, int buf) {
        for (int idx = tid; idx < 1024; idx += 128) {
            int c = idx & 15, co = idx >> 4;
            cp_async4(&s_w[buf][c][co], &w[co * Cin + ci0 + c]);
        }
        cp_commit();
    };

    const int nch = Cin >> 4;
    load_w(0, 0);
    for (int it = 0; it < nch; it++) {
        const int buf = it & 1;
        if (it + 1 < nch) { load_w((it + 1) * 16, buf ^ 1); cp_wait<1>(); }
        else cp_wait<0>();
        __syncthreads();
        const int ci0 = it * 16;
#pragma unroll 4
        for (int c = 0; c < 16; c++) {
            const int ci = ci0 + c;
            float val;
            if (MODE == 0) {
                if (ci < CA)
                    val = inA[(n * CA + ci) * HW + hw];
                else
                    val = inB[(n * CB + (ci - CA)) * HW + hw];
            } else {
                const int off = (n * CA + ci) * HW + hw;
                val = fmaxf(inA[off] + inB[off] + __ldg(&cbias[ci]), 0.f);
            }
            const u64t vp = packdup(val);
            const ulonglong2* wr = (const ulonglong2*)s_w[buf][c];
#pragma unroll
            for (int j = 0; j < 16; j++) {
                const ulonglong2 wv = wr[j];
                ffma2(f2[2 * j + 0], vp, wv.x);
                ffma2(f2[2 * j + 1], vp, wv.y);
            }
        }
        __syncthreads();
    }
    // bias
    float f[64];
#pragma unroll
    for (int i = 0; i < 32; i++) {
        const float2 pv = unpk(f2[i]);
        f[2 * i] = pv.x + b[2 * i];
        f[2 * i + 1] = pv.y + b[2 * i + 1];
        f2[i] = pack2(f[2 * i], f[2 * i + 1]);
    }

    auto load_e = [&](int k0, int buf) {
        for (int idx = tid; idx < 4096; idx += 128) {
            int d = idx >> 6, k = idx & 63;
            cp_async4(&s_e[buf][k][d], &embed[d * 512 + k0 + k]);
        }
        if (tid < 64) cp_async4(&s_n[buf][tid], &norms[k0 + tid]);
        cp_commit();
    };

    float best = 3.4e38f;
    int bid = 0;
    load_e(0, 0);
    for (int it = 0; it < 8; it++) {
        const int buf = it & 1;
        if (it + 1 < 8) { load_e((it + 1) * 64, buf ^ 1); cp_wait<1>(); }
        else cp_wait<0>();
        __syncthreads();
        const int k0 = it * 64;
        for (int k = 0; k < 64; k++) {
            u64t d0 = 0ull, d1 = 0ull;
            const ulonglong2* er = (const ulonglong2*)s_e[buf][k];
#pragma unroll
            for (int j = 0; j < 16; j++) {
                const ulonglong2 e = er[j];
                ffma2(d0, f2[2 * j + 0], e.x);
                ffma2(d1, f2[2 * j + 1], e.y);
            }
            const float2 a0 = unpk(d0), a1 = unpk(d1);
            const float sc = s_n[buf][k] - 2.f * ((a0.x + a0.y) + (a1.x + a1.y));
            if (sc < best) { best = sc; bid = k0 + k; }
        }
        __syncthreads();
    }

    float lsum = 0.f;
#pragma unroll
    for (int d = 0; d < 64; d++) {
        const float q = __ldg(&embed[d * 512 + bid]);
        const float df = q - f[d];
        lsum = fmaf(df, df, lsum);
        qout[(n * 64 + d) * HW + hw] = q;
    }
    idout[v] = (float)bid;
#pragma unroll
    for (int o = 16; o > 0; o >>= 1) lsum += __shfl_down_sync(0xffffffffu, lsum, o);
    if ((tid & 31) == 0) atomicAdd(acc, lsum);
}

__global__ void finalize_loss_kernel(const float* __restrict__ acc, float* __restrict__ o) {
    o[0] = acc[0] * (1.f / 1048576.f) + acc[1] * (1.f / 4194304.f);
}

extern "C" void kernel_launch(void* const* d_in, const int* in_sizes, int n_in,
                              void* d_out, int out_size) {
    (void)in_sizes; (void)n_in; (void)out_size;
    const float* x       = (const float*)d_in[0];
    const float* wb1     = (const float*)d_in[1];
    const float* bb1     = (const float*)d_in[2];
    const float* wb2     = (const float*)d_in[3];
    const float* bb2     = (const float*)d_in[4];
    const float* wt1     = (const float*)d_in[5];
    const float* bt1     = (const float*)d_in[6];
    const float* wqt     = (const float*)d_in[7];
    const float* bqt     = (const float*)d_in[8];
    const float* embed_t = (const float*)d_in[9];
    const float* wdt     = (const float*)d_in[10];
    const float* bdt     = (const float*)d_in[11];
    const float* wqb     = (const float*)d_in[12];
    const float* bqb     = (const float*)d_in[13];
    const float* embed_b = (const float*)d_in[14];
    const float* wup     = (const float*)d_in[15];
    const float* bup     = (const float*)d_in[16];
    const float* wd1     = (const float*)d_in[17];
    const float* bd1     = (const float*)d_in[18];
    const float* wd2     = (const float*)d_in[19];
    const float* bd2     = (const float*)d_in[20];

    float* out    = (float*)d_out;
    float* o_xhat = out;
    float* o_qt   = out + 3145728;
    float* o_qb   = out + 4194304;
    float* o_loss = out + 8388608;
    float* o_idt  = out + 8388609;
    float* o_idb  = out + 8404993;

    float *encb1, *encb, *enct, *dect, *upt, *h, *normt, *normb, *acc;
    cudaGetSymbolAddress((void**)&encb1, g_encb1);
    cudaGetSymbolAddress((void**)&encb,  g_encb);
    cudaGetSymbolAddress((void**)&enct,  g_enct);
    cudaGetSymbolAddress((void**)&dect,  g_dect);
    cudaGetSymbolAddress((void**)&upt,   g_upt);
    cudaGetSymbolAddress((void**)&h,     g_h);
    cudaGetSymbolAddress((void**)&normt, g_normt);
    cudaGetSymbolAddress((void**)&normb, g_normb);
    cudaGetSymbolAddress((void**)&acc,   g_acc);

    init_kernel<<<1, 512>>>(embed_t, embed_b, normt, normb, acc);

    // ---- encoder ----
    conv4x4s2_kernel<true, 1><<<dim3(8, 8, 16 * 4), 128>>>(x, wb1, bb1, encb1, 16, 3, 128, 256, 256);
    conv4x4s2_kernel<true, 1><<<dim3(4, 4, 16 * 4), 128>>>(encb1, wb2, bb2, encb, 16, 128, 128, 128, 128);
    // conv3: split-K x2 -> partials; bias+relu fused into quant_t input
    conv4x4s2_kernel<false, 2><<<dim3(2, 2, 16 * 4 * 2), 128>>>(encb, wt1, nullptr, enct, 16, 128, 128, 64, 64);

    // ---- top quantize (reads relu(p0+p1+bt1)) ----
    conv1x1_quantize_kernel<1><<<16384 / 128, 128>>>(enct, enct + 2097152, 128, 0, bt1,
                                                     wqt, bqt, embed_t, normt, o_qt, o_idt, acc + 0, 1024);

    // ---- decoder_top + upsample_t fused (both read quant_t) ----
    convT4x4_kernel<false, true><<<dim3(4, 4, 16 * 4), 128>>>(
        o_qt, o_qt, 64, wdt, bdt, dect, wup, bup, upt, 16, 64, 64, 32, 32);

    // ---- bottom quantize ----
    conv1x1_quantize_kernel<0><<<65536 / 128, 128>>>(dect, encb, 64, 128, nullptr,
                                                     wqb, bqb, embed_b, normb, o_qb, o_idb, acc + 1, 4096);

    // ---- decode ----
    convT4x4_kernel<true, false><<<dim3(8, 8, 16 * 2), 128>>>(
        upt, o_qb, 64, wd1, bd1, h, nullptr, nullptr, nullptr, 16, 128, 64, 64, 64);
    convT4x4_small_kernel<<<dim3(8, 8, 16), 256>>>(h, wd2, bd2, o_xhat, 16, 64, 128, 128);

    finalize_loss_kernel<<<1, 1>>>(acc, o_loss);
}

// round 12
// speedup vs baseline: 1.1300x; 1.1300x over previous
#include <cuda_runtime.h>
#include <cuda_bf16.h>

typedef unsigned long long u64t;

__device__ __forceinline__ void ffma2(u64t& d, u64t a, u64t b) {
    asm("fma.rn.f32x2 %0, %1, %2, %0;" : "+l"(d) : "l"(a), "l"(b));
}
__device__ __forceinline__ u64t packdup(float v) {
    u64t r;
    asm("mov.b64 %0, {%1, %1};" : "=l"(r) : "r"(__float_as_uint(v)));
    return r;
}
__device__ __forceinline__ u64t pack2(float a, float b) {
    u64t r;
    asm("mov.b64 %0, {%1, %2};" : "=l"(r) : "r"(__float_as_uint(a)), "r"(__float_as_uint(b)));
    return r;
}
__device__ __forceinline__ float2 unpk(u64t p) {
    unsigned lo, hi;
    asm("mov.b64 {%0, %1}, %2;" : "=r"(lo), "=r"(hi) : "l"(p));
    return make_float2(__uint_as_float(lo), __uint_as_float(hi));
}
__device__ __forceinline__ void cp_async4(void* smem, const void* gmem) {
    unsigned s = (unsigned)__cvta_generic_to_shared(smem);
    asm volatile("cp.async.ca.shared.global [%0], [%1], 4;" :: "r"(s), "l"(gmem));
}
__device__ __forceinline__ void cp_commit() {
    asm volatile("cp.async.commit_group;" ::: "memory");
}
template <int N>
__device__ __forceinline__ void cp_wait() {
    asm volatile("cp.async.wait_group %0;" :: "n"(N) : "memory");
}

__device__ float g_encb1[16 * 128 * 128 * 128];
__device__ float g_encb [16 * 128 * 64 * 64];
__device__ float g_enct [4 * 16 * 128 * 32 * 32];   // split-K x4 partials for conv3
__device__ float g_dect [16 * 64 * 64 * 64];
__device__ float g_upt  [16 * 64 * 64 * 64];
__device__ float g_h    [16 * 64 * 128 * 128];
__device__ float g_normt[512];
__device__ float g_normb[512];
__device__ float g_acc[2];

#define ENCT_STRIDE 2097152  // 16*128*32*32

__global__ void init_kernel(const float* __restrict__ et, const float* __restrict__ eb,
                            float* __restrict__ nt, float* __restrict__ nb,
                            float* __restrict__ acc) {
    int k = threadIdx.x; // 512 threads
    float st = 0.f, sb = 0.f;
#pragma unroll
    for (int d = 0; d < 64; d++) {
        float a = et[d * 512 + k]; st = fmaf(a, a, st);
        float b = eb[d * 512 + k]; sb = fmaf(b, b, sb);
    }
    nt[k] = st;
    nb[k] = sb;
    if (k < 2) acc[k] = 0.f;
}

// ---------------------------------------------------------------------------
// 4x4 stride-2 pad-1 conv (+relu). 128 threads = 4 lane4 x 4 sx x 8 sy.
// Each thread: 2x4 output pixels x 8 couts. Output tile 16x16.
// Fast path: compile-time channel loop (unroll 2) for software pipelining.
// ---------------------------------------------------------------------------
#define CCHNK 4
template <bool RELU, int KS>
__global__ __launch_bounds__(128, 4) void conv4x4s2_kernel(
    const float* __restrict__ in, const float* __restrict__ w,
    const float* __restrict__ bias, float* __restrict__ out,
    int N, int Cin, int Cout, int Hin, int Win) {
    const int Hout = Hin >> 1, Wout = Win >> 1;
    const int tid = threadIdx.x;
    const int lane4 = tid & 3;
    const int sp = tid >> 2;             // 0..31
    const int sx = sp & 3, sy = sp >> 2; // sx 0..3, sy 0..7
    const int ox0 = blockIdx.x << 4, oy0 = blockIdx.y << 4;
    const int cog = Cout >> 5;
    const int zdiv = cog * KS;
    const int n = blockIdx.z / zdiv;
    const int rem = blockIdx.z % zdiv;
    const int ks = rem / cog;
    const int co0 = (rem % cog) << 5;
    const int CinL = Cin / KS;
    const int ciBase = ks * CinL;
    float* outp = out + (size_t)ks * N * Cout * Hout * Wout;

    __shared__ float s_in[2][CCHNK][34][34];
    __shared__ float s_w[2][CCHNK][16][36];

    u64t acc2[8][4];
#pragma unroll
    for (int p = 0; p < 8; p++)
#pragma unroll
        for (int j = 0; j < 4; j++) acc2[p][j] = 0ull;

    const int iyb = 2 * oy0 - 1, ixb = 2 * ox0 - 1;
    const int by = 4 * sy, bx = 8 * sx;

    for (int idx = tid; idx < 2 * CCHNK * 1156; idx += 128)
        ((float*)s_in)[idx] = 0.f;
    __syncthreads();

    auto load_chunk = [&](int ci0, int buf) {
        const int cc = min(CCHNK, CinL - ci0);
        for (int idx = tid; idx < cc * 1156; idx += 128) {
            int c = idx / 1156, r = idx - c * 1156;
            int yy = r / 34, xx = r - yy * 34;
            int iy = iyb + yy, ix = ixb + xx;
            if ((unsigned)iy < (unsigned)Hin && (unsigned)ix < (unsigned)Win)
                cp_async4(&s_in[buf][c][yy][xx],
                          &in[((n * Cin + ciBase + ci0 + c) * Hin + iy) * Win + ix]);
        }
        const int cseg = cc * 16;
        for (int idx = tid; idx < cc * 512; idx += 128) {
            int co = idx / cseg;
            int r = idx - co * cseg;
            int c = r >> 4, kk = r & 15;
            cp_async4(&s_w[buf][c][kk][co],
                      &w[(co0 + co) * Cin * 16 + (ciBase + ci0) * 16 + r]);
        }
        cp_commit();
    };

    auto body = [&](int buf, int c) {
#pragma unroll
        for (int kk = 0; kk < 16; kk++) {
            const int ky = kk >> 2, kx = kk & 3;
            u64t vp[8];
#pragma unroll
            for (int dy = 0; dy < 2; dy++)
#pragma unroll
                for (int dx = 0; dx < 4; dx++)
                    vp[dy * 4 + dx] = packdup(s_in[buf][c][by + 2 * dy + ky][bx + 2 * dx + kx]);
            const float* wp = &s_w[buf][c][kk][lane4 * 8];
            const ulonglong2 wA = *(const ulonglong2*)(wp);
            const ulonglong2 wB = *(const ulonglong2*)(wp + 4);
            const u64t wv[4] = {wA.x, wA.y, wB.x, wB.y};
#pragma unroll
            for (int j = 0; j < 4; j++)
#pragma unroll
                for (int p = 0; p < 8; p++)
                    ffma2(acc2[p][j], vp[p], wv[j]);
        }
    };

    const int nch = (CinL + CCHNK - 1) / CCHNK;
    load_chunk(0, 0);
    for (int it = 0; it < nch; it++) {
        const int buf = it & 1;
        if (it + 1 < nch) { load_chunk((it + 1) * CCHNK, buf ^ 1); cp_wait<1>(); }
        else cp_wait<0>();
        __syncthreads();
        const int cc = min(CCHNK, CinL - it * CCHNK);
        if (cc == CCHNK) {
#pragma unroll 2
            for (int c = 0; c < CCHNK; c++) body(buf, c);
        } else {
            for (int c = 0; c < cc; c++) body(buf, c);
        }
        __syncthreads();
    }
#pragma unroll
    for (int dy = 0; dy < 2; dy++)
#pragma unroll
        for (int dx = 0; dx < 4; dx++) {
            const int oy = oy0 + 2 * sy + dy, ox = ox0 + 4 * sx + dx;
#pragma unroll
            for (int j = 0; j < 4; j++) {
                const int co = co0 + lane4 * 8 + 2 * j;
                const float2 pv = unpk(acc2[dy * 4 + dx][j]);
                float r0 = pv.x, r1 = pv.y;
                if (KS == 1) { r0 += bias[co]; r1 += bias[co + 1]; }
                if (RELU) { r0 = fmaxf(r0, 0.f); r1 = fmaxf(r1, 0.f); }
                outp[((n * Cout + co) * Hout + oy) * Wout + ox] = r0;
                outp[((n * Cout + co + 1) * Hout + oy) * Wout + ox] = r1;
            }
        }
}

// ---------------------------------------------------------------------------
// convT. 128 threads; 2x4 output pixels x 8 couts; unrolled channel fast path.
// DUAL: dect+upt fusion (two weight/output sets share input tile).
// ---------------------------------------------------------------------------
#define TCHNK 8
template <bool RELU, bool DUAL>
__global__ __launch_bounds__(128, 4) void convT4x4_kernel(
    const float* __restrict__ inA, const float* __restrict__ inB, int CA,
    const float* __restrict__ w, const float* __restrict__ bias,
    float* __restrict__ out,
    const float* __restrict__ w2, const float* __restrict__ bias2,
    float* __restrict__ out2,
    int N, int Cin, int Cout, int Hin, int Win) {
    const int Hout = Hin << 1, Wout = Win << 1;
    const int tid = threadIdx.x;
    const int lane4 = tid & 3;
    const int sp = tid >> 2;
    const int sx = sp & 3, sy = sp >> 2; // sx 0..3, sy 0..7
    const int ox0 = blockIdx.x << 4, oy0 = blockIdx.y << 4;
    const int cog = Cout >> 5;
    const int zdiv = cog * (DUAL ? 2 : 1);
    const int n = blockIdx.z / zdiv;
    int g = blockIdx.z % zdiv;
    const float* wU = w;
    const float* bU = bias;
    float* oU = out;
    if (DUAL && g >= cog) { wU = w2; bU = bias2; oU = out2; g -= cog; }
    const int co0 = g << 5;
    const int CB = Cin - CA;

    __shared__ float s_in[2][TCHNK][10][10];
    __shared__ float s_w[2][TCHNK][16][36];

    u64t acc2[8][4];
#pragma unroll
    for (int p = 0; p < 8; p++)
#pragma unroll
        for (int j = 0; j < 4; j++) acc2[p][j] = 0ull;

    const int iy0 = (oy0 >> 1) - 1, ix0 = (ox0 >> 1) - 1;

    for (int idx = tid; idx < 2 * TCHNK * 100; idx += 128)
        ((float*)s_in)[idx] = 0.f;
    __syncthreads();

    auto load_chunk = [&](int ci0, int buf) {
        const int cc = min(TCHNK, Cin - ci0);
        for (int idx = tid; idx < cc * 100; idx += 128) {
            int c = idx / 100, r = idx - c * 100;
            int yy = r / 10, xx = r - yy * 10;
            int iy = iy0 + yy, ix = ix0 + xx;
            int ci = ci0 + c;
            if ((unsigned)iy < (unsigned)Hin && (unsigned)ix < (unsigned)Win) {
                const float* src = (ci < CA)
                    ? &inA[((n * CA + ci) * Hin + iy) * Win + ix]
                    : &inB[((n * CB + (ci - CA)) * Hin + iy) * Win + ix];
                cp_async4(&s_in[buf][c][yy][xx], src);
            }
        }
        for (int idx = tid; idx < cc * 512; idx += 128) {
            int c = idx >> 9, r = idx & 511; // r = co*16 + kk
            int co = r >> 4, kk = r & 15;
            cp_async4(&s_w[buf][c][kk][co], &wU[(ci0 + c) * Cout * 16 + co0 * 16 + r]);
        }
        cp_commit();
    };

    auto body = [&](int buf, int c) {
        // register tile: rows sy..sy+2, cols 2sx..2sx+3
        u64t vin[3][4];
#pragma unroll
        for (int i = 0; i < 3; i++)
#pragma unroll
            for (int j2 = 0; j2 < 4; j2++)
                vin[i][j2] = packdup(s_in[buf][c][sy + i][2 * sx + j2]);
#pragma unroll
        for (int kk = 0; kk < 16; kk++) {
            const int ky = kk >> 2, kx = kk & 3;
            const int dy = (ky & 1) ? 0 : 1;
            const int ry = (ky & 1) ? (1 - ((ky - 1) >> 1)) : (2 - (ky >> 1));
            const int dxx0 = (kx & 1) ? 0 : 1;          // first matching out-col offset
            const int c0 = ((dxx0 + 1 - kx) >> 1) + 1;  // vin col for dxx0 (0..2)
            const u64t va = vin[ry][c0];
            const u64t vb = vin[ry][c0 + 1];            // for dxx0 + 2
            const float* wp = &s_w[buf][c][kk][lane4 * 8];
            const ulonglong2 wA = *(const ulonglong2*)(wp);
            const ulonglong2 wB = *(const ulonglong2*)(wp + 4);
            const u64t wv[4] = {wA.x, wA.y, wB.x, wB.y};
            u64t* aa = acc2[dy * 4 + dxx0];
            u64t* ab = acc2[dy * 4 + dxx0 + 2];
#pragma unroll
            for (int j = 0; j < 4; j++) {
                ffma2(aa[j], va, wv[j]);
                ffma2(ab[j], vb, wv[j]);
            }
        }
    };

    const int nch = (Cin + TCHNK - 1) / TCHNK;
    load_chunk(0, 0);
    for (int it = 0; it < nch; it++) {
        const int buf = it & 1;
        if (it + 1 < nch) { load_chunk((it + 1) * TCHNK, buf ^ 1); cp_wait<1>(); }
        else cp_wait<0>();
        __syncthreads();
        const int cc = min(TCHNK, Cin - it * TCHNK);
        if (cc == TCHNK) {
#pragma unroll 2
            for (int c = 0; c < TCHNK; c++) body(buf, c);
        } else {
            for (int c = 0; c < cc; c++) body(buf, c);
        }
        __syncthreads();
    }
#pragma unroll
    for (int dy = 0; dy < 2; dy++)
#pragma unroll
        for (int dx = 0; dx < 4; dx++) {
            const int oy = oy0 + 2 * sy + dy, ox = ox0 + 4 * sx + dx;
#pragma unroll
            for (int j = 0; j < 4; j++) {
                const int co = co0 + lane4 * 8 + 2 * j;
                const float2 pv = unpk(acc2[dy * 4 + dx][j]);
                float r0 = pv.x + bU[co];
                float r1 = pv.y + bU[co + 1];
                if (RELU) { r0 = fmaxf(r0, 0.f); r1 = fmaxf(r1, 0.f); }
                oU[((n * Cout + co) * Hout + oy) * Wout + ox] = r0;
                oU[((n * Cout + co + 1) * Hout + oy) * Wout + ox] = r1;
            }
        }
}

// ---------------------------------------------------------------------------
// ConvT small (Cout=3), cp.async double-buffered (proven version)
// ---------------------------------------------------------------------------
#define SCHNK 8
__global__ __launch_bounds__(256) void convT4x4_small_kernel(
    const float* __restrict__ in, const float* __restrict__ w,
    const float* __restrict__ bias, float* __restrict__ out,
    int N, int Cin, int Hin, int Win) {
    const int Hout = Hin << 1, Wout = Win << 1;
    const int tid = threadIdx.x;
    const int sx = tid & 15, sy = tid >> 4;
    const int ox0 = blockIdx.x << 5, oy0 = blockIdx.y << 5;
    const int n = blockIdx.z;

    __shared__ float s_in[2][SCHNK][18][18];
    __shared__ float s_w[2][SCHNK][16][4];

    u64t acc01[4];
    float acc2s[4];
#pragma unroll
    for (int p = 0; p < 4; p++) { acc01[p] = 0ull; acc2s[p] = 0.f; }

    const int iy0 = (oy0 >> 1) - 1, ix0 = (ox0 >> 1) - 1;

    for (int idx = tid; idx < 2 * SCHNK * 324; idx += 256)
        ((float*)s_in)[idx] = 0.f;
    __syncthreads();

    auto load_chunk = [&](int ci0, int buf) {
        const int cc = min(SCHNK, Cin - ci0);
        for (int idx = tid; idx < cc * 324; idx += 256) {
            int c = idx / 324, r = idx - c * 324;
            int yy = r / 18, xx = r - yy * 18;
            int iy = iy0 + yy, ix = ix0 + xx;
            if ((unsigned)iy < (unsigned)Hin && (unsigned)ix < (unsigned)Win)
                cp_async4(&s_in[buf][c][yy][xx],
                          &in[((n * Cin + ci0 + c) * Hin + iy) * Win + ix]);
        }
        for (int idx = tid; idx < cc * 48; idx += 256) {
            int c = idx / 48, r = idx - c * 48;
            int co = r >> 4, kk = r & 15;
            cp_async4(&s_w[buf][c][kk][co], &w[(ci0 + c) * 3 * 16 + r]);
        }
        cp_commit();
    };

    const int nch = (Cin + SCHNK - 1) / SCHNK;
    load_chunk(0, 0);
    for (int it = 0; it < nch; it++) {
        const int buf = it & 1;
        if (it + 1 < nch) { load_chunk((it + 1) * SCHNK, buf ^ 1); cp_wait<1>(); }
        else cp_wait<0>();
        __syncthreads();
        const int cc = min(SCHNK, Cin - it * SCHNK);
        for (int c = 0; c < cc; c++) {
            float vin[3][3];
#pragma unroll
            for (int i = 0; i < 3; i++)
#pragma unroll
                for (int j2 = 0; j2 < 3; j2++) vin[i][j2] = s_in[buf][c][sy + i][sx + j2];
#pragma unroll
            for (int kk = 0; kk < 16; kk++) {
                const int ky = kk >> 2, kx = kk & 3;
                const int dy = (ky & 1) ? 0 : 1;
                const int ry = (ky & 1) ? (1 - ((ky - 1) >> 1)) : (2 - (ky >> 1));
                const int dx = (kx & 1) ? 0 : 1;
                const int rx = (kx & 1) ? (1 - ((kx - 1) >> 1)) : (2 - (kx >> 1));
                const float vs = vin[ry][rx];
                const u64t v = packdup(vs);
                const u64t w01 = *(const u64t*)&s_w[buf][c][kk][0];
                const int p = dy * 2 + dx;
                ffma2(acc01[p], v, w01);
                acc2s[p] = fmaf(vs, s_w[buf][c][kk][2], acc2s[p]);
            }
        }
        __syncthreads();
    }
#pragma unroll
    for (int dy = 0; dy < 2; dy++)
#pragma unroll
        for (int dx = 0; dx < 2; dx++) {
            const int oy = oy0 + 2 * sy + dy, ox = ox0 + 2 * sx + dx;
            const float2 pv = unpk(acc01[dy * 2 + dx]);
            out[((n * 3 + 0) * Hout + oy) * Wout + ox] = pv.x + bias[0];
            out[((n * 3 + 1) * Hout + oy) * Wout + ox] = pv.y + bias[1];
            out[((n * 3 + 2) * Hout + oy) * Wout + ox] = acc2s[dy * 2 + dx] + bias[2];
        }
}

// ---------------------------------------------------------------------------
// Fused 1x1 conv + VQ. 128 threads/block, 64-wide codebook chunks.
// MODE 0: concat input. MODE 1: relu(sum of 4 split-K partials + cbias).
// ---------------------------------------------------------------------------
template <int MODE>
__global__ __launch_bounds__(128) void conv1x1_quantize_kernel(
    const float* __restrict__ inA, const float* __restrict__ inB, int CA, int CB,
    const float* __restrict__ cbias,
    const float* __restrict__ w, const float* __restrict__ b,
    const float* __restrict__ embed, const float* __restrict__ norms,
    float* __restrict__ qout, float* __restrict__ idout, float* __restrict__ acc,
    int HW) {
    const int tid = threadIdx.x;
    const int v = blockIdx.x * 128 + tid;
    const int n = v / HW, hw = v - n * HW;
    const int Cin = (MODE == 0) ? (CA + CB) : CA;

    __shared__ float s_w[2][16][68];
    __shared__ float s_e[2][64][68];
    __shared__ float s_n[2][64];

    u64t f2[32];
#pragma unroll
    for (int i = 0; i < 32; i++) f2[i] = 0ull;

    auto load_w = [&](int ci0, int buf) {
        for (int idx = tid; idx < 1024; idx += 128) {
            int c = idx & 15, co = idx >> 4;
            cp_async4(&s_w[buf][c][co], &w[co * Cin + ci0 + c]);
        }
        cp_commit();
    };

    const int nch = Cin >> 4;
    load_w(0, 0);
    for (int it = 0; it < nch; it++) {
        const int buf = it & 1;
        if (it + 1 < nch) { load_w((it + 1) * 16, buf ^ 1); cp_wait<1>(); }
        else cp_wait<0>();
        __syncthreads();
        const int ci0 = it * 16;
#pragma unroll 4
        for (int c = 0; c < 16; c++) {
            const int ci = ci0 + c;
            float val;
            if (MODE == 0) {
                if (ci < CA)
                    val = inA[(n * CA + ci) * HW + hw];
                else
                    val = inB[(n * CB + (ci - CA)) * HW + hw];
            } else {
                const int off = (n * CA + ci) * HW + hw;
                val = fmaxf(((inA[off] + inA[off + ENCT_STRIDE]) +
                             (inA[off + 2 * ENCT_STRIDE] + inA[off + 3 * ENCT_STRIDE])) +
                            __ldg(&cbias[ci]), 0.f);
            }
            const u64t vp = packdup(val);
            const ulonglong2* wr = (const ulonglong2*)s_w[buf][c];
#pragma unroll
            for (int j = 0; j < 16; j++) {
                const ulonglong2 wv = wr[j];
                ffma2(f2[2 * j + 0], vp, wv.x);
                ffma2(f2[2 * j + 1], vp, wv.y);
            }
        }
        __syncthreads();
    }
    // bias
    float f[64];
#pragma unroll
    for (int i = 0; i < 32; i++) {
        const float2 pv = unpk(f2[i]);
        f[2 * i] = pv.x + b[2 * i];
        f[2 * i + 1] = pv.y + b[2 * i + 1];
        f2[i] = pack2(f[2 * i], f[2 * i + 1]);
    }

    auto load_e = [&](int k0, int buf) {
        for (int idx = tid; idx < 4096; idx += 128) {
            int d = idx >> 6, k = idx & 63;
            cp_async4(&s_e[buf][k][d], &embed[d * 512 + k0 + k]);
        }
        if (tid < 64) cp_async4(&s_n[buf][tid], &norms[k0 + tid]);
        cp_commit();
    };

    float best = 3.4e38f;
    int bid = 0;
    load_e(0, 0);
    for (int it = 0; it < 8; it++) {
        const int buf = it & 1;
        if (it + 1 < 8) { load_e((it + 1) * 64, buf ^ 1); cp_wait<1>(); }
        else cp_wait<0>();
        __syncthreads();
        const int k0 = it * 64;
        for (int k = 0; k < 64; k++) {
            u64t d0 = 0ull, d1 = 0ull;
            const ulonglong2* er = (const ulonglong2*)s_e[buf][k];
#pragma unroll
            for (int j = 0; j < 16; j++) {
                const ulonglong2 e = er[j];
                ffma2(d0, f2[2 * j + 0], e.x);
                ffma2(d1, f2[2 * j + 1], e.y);
            }
            const float2 a0 = unpk(d0), a1 = unpk(d1);
            const float sc = s_n[buf][k] - 2.f * ((a0.x + a0.y) + (a1.x + a1.y));
            if (sc < best) { best = sc; bid = k0 + k; }
        }
        __syncthreads();
    }

    float lsum = 0.f;
#pragma unroll
    for (int d = 0; d < 64; d++) {
        const float q = __ldg(&embed[d * 512 + bid]);
        const float df = q - f[d];
        lsum = fmaf(df, df, lsum);
        qout[(n * 64 + d) * HW + hw] = q;
    }
    idout[v] = (float)bid;
#pragma unroll
    for (int o = 16; o > 0; o >>= 1) lsum += __shfl_down_sync(0xffffffffu, lsum, o);
    if ((tid & 31) == 0) atomicAdd(acc, lsum);
}

__global__ void finalize_loss_kernel(const float* __restrict__ acc, float* __restrict__ o) {
    o[0] = acc[0] * (1.f / 1048576.f) + acc[1] * (1.f / 4194304.f);
}

extern "C" void kernel_launch(void* const* d_in, const int* in_sizes, int n_in,
                              void* d_out, int out_size) {
    (void)in_sizes; (void)n_in; (void)out_size;
    const float* x       = (const float*)d_in[0];
    const float* wb1     = (const float*)d_in[1];
    const float* bb1     = (const float*)d_in[2];
    const float* wb2     = (const float*)d_in[3];
    const float* bb2     = (const float*)d_in[4];
    const float* wt1     = (const float*)d_in[5];
    const float* bt1     = (const float*)d_in[6];
    const float* wqt     = (const float*)d_in[7];
    const float* bqt     = (const float*)d_in[8];
    const float* embed_t = (const float*)d_in[9];
    const float* wdt     = (const float*)d_in[10];
    const float* bdt     = (const float*)d_in[11];
    const float* wqb     = (const float*)d_in[12];
    const float* bqb     = (const float*)d_in[13];
    const float* embed_b = (const float*)d_in[14];
    const float* wup     = (const float*)d_in[15];
    const float* bup     = (const float*)d_in[16];
    const float* wd1     = (const float*)d_in[17];
    const float* bd1     = (const float*)d_in[18];
    const float* wd2     = (const float*)d_in[19];
    const float* bd2     = (const float*)d_in[20];

    float* out    = (float*)d_out;
    float* o_xhat = out;
    float* o_qt   = out + 3145728;
    float* o_qb   = out + 4194304;
    float* o_loss = out + 8388608;
    float* o_idt  = out + 8388609;
    float* o_idb  = out + 8404993;

    float *encb1, *encb, *enct, *dect, *upt, *h, *normt, *normb, *acc;
    cudaGetSymbolAddress((void**)&encb1, g_encb1);
    cudaGetSymbolAddress((void**)&encb,  g_encb);
    cudaGetSymbolAddress((void**)&enct,  g_enct);
    cudaGetSymbolAddress((void**)&dect,  g_dect);
    cudaGetSymbolAddress((void**)&upt,   g_upt);
    cudaGetSymbolAddress((void**)&h,     g_h);
    cudaGetSymbolAddress((void**)&normt, g_normt);
    cudaGetSymbolAddress((void**)&normb, g_normb);
    cudaGetSymbolAddress((void**)&acc,   g_acc);

    init_kernel<<<1, 512>>>(embed_t, embed_b, normt, normb, acc);

    // ---- encoder ----
    conv4x4s2_kernel<true, 1><<<dim3(8, 8, 16 * 4), 128>>>(x, wb1, bb1, encb1, 16, 3, 128, 256, 256);
    conv4x4s2_kernel<true, 1><<<dim3(4, 4, 16 * 4), 128>>>(encb1, wb2, bb2, encb, 16, 128, 128, 128, 128);
    // conv3: split-K x4 -> partials; bias+relu fused into quant_t input
    conv4x4s2_kernel<false, 4><<<dim3(2, 2, 16 * 4 * 4), 128>>>(encb, wt1, nullptr, enct, 16, 128, 128, 64, 64);

    // ---- top quantize (reads relu(p0+p1+p2+p3+bt1)) ----
    conv1x1_quantize_kernel<1><<<16384 / 128, 128>>>(enct, nullptr, 128, 0, bt1,
                                                     wqt, bqt, embed_t, normt, o_qt, o_idt, acc + 0, 1024);

    // ---- decoder_top + upsample_t fused (both read quant_t) ----
    convT4x4_kernel<false, true><<<dim3(4, 4, 16 * 4), 128>>>(
        o_qt, o_qt, 64, wdt, bdt, dect, wup, bup, upt, 16, 64, 64, 32, 32);

    // ---- bottom quantize ----
    conv1x1_quantize_kernel<0><<<65536 / 128, 128>>>(dect, encb, 64, 128, nullptr,
                                                     wqb, bqb, embed_b, normb, o_qb, o_idb, acc + 1, 4096);

    // ---- decode ----
    convT4x4_kernel<true, false><<<dim3(8, 8, 16 * 2), 128>>>(
        upt, o_qb, 64, wd1, bd1, h, nullptr, nullptr, nullptr, 16, 128, 64, 64, 64);
    convT4x4_small_kernel<<<dim3(8, 8, 16), 256>>>(h, wd2, bd2, o_xhat, 16, 64, 128, 128);

    finalize_loss_kernel<<<1, 1>>>(acc, o_loss);
}

// round 13
// speedup vs baseline: 1.1599x; 1.0265x over previous
#include <cuda_runtime.h>
#include <cuda_bf16.h>

typedef unsigned long long u64t;

__device__ __forceinline__ void ffma2(u64t& d, u64t a, u64t b) {
    asm("fma.rn.f32x2 %0, %1, %2, %0;" : "+l"(d) : "l"(a), "l"(b));
}
__device__ __forceinline__ u64t packdup(float v) {
    u64t r;
    asm("mov.b64 %0, {%1, %1};" : "=l"(r) : "r"(__float_as_uint(v)));
    return r;
}
__device__ __forceinline__ u64t pack2(float a, float b) {
    u64t r;
    asm("mov.b64 %0, {%1, %2};" : "=l"(r) : "r"(__float_as_uint(a)), "r"(__float_as_uint(b)));
    return r;
}
__device__ __forceinline__ float2 unpk(u64t p) {
    unsigned lo, hi;
    asm("mov.b64 {%0, %1}, %2;" : "=r"(lo), "=r"(hi) : "l"(p));
    return make_float2(__uint_as_float(lo), __uint_as_float(hi));
}
__device__ __forceinline__ void cp_async4(void* smem, const void* gmem) {
    unsigned s = (unsigned)__cvta_generic_to_shared(smem);
    asm volatile("cp.async.ca.shared.global [%0], [%1], 4;" :: "r"(s), "l"(gmem));
}
__device__ __forceinline__ void cp_commit() {
    asm volatile("cp.async.commit_group;" ::: "memory");
}
template <int N>
__device__ __forceinline__ void cp_wait() {
    asm volatile("cp.async.wait_group %0;" :: "n"(N) : "memory");
}

__device__ float g_encb1[16 * 128 * 128 * 128];
__device__ float g_encb [16 * 128 * 64 * 64];
__device__ float g_enct [4 * 16 * 128 * 32 * 32];   // split-K x4 partials for conv3
__device__ float g_dect [16 * 64 * 64 * 64];
__device__ float g_upt  [16 * 64 * 64 * 64];
__device__ float g_h    [16 * 64 * 128 * 128];
__device__ float g_normt[512];
__device__ float g_normb[512];
__device__ float g_acc[2];

#define ENCT_STRIDE 2097152  // 16*128*32*32

__global__ void init_kernel(const float* __restrict__ et, const float* __restrict__ eb,
                            float* __restrict__ nt, float* __restrict__ nb,
                            float* __restrict__ acc) {
    int k = threadIdx.x; // 512 threads
    float st = 0.f, sb = 0.f;
#pragma unroll
    for (int d = 0; d < 64; d++) {
        float a = et[d * 512 + k]; st = fmaf(a, a, st);
        float b = eb[d * 512 + k]; sb = fmaf(b, b, sb);
    }
    nt[k] = st;
    nb[k] = sb;
    if (k < 2) acc[k] = 0.f;
}

// ---------------------------------------------------------------------------
// 4x4 stride-2 pad-1 conv (+relu). 128 threads = 4 lane4 x 4 sx x 8 sy.
// Each thread: 2x4 output pixels x 8 couts. Output tile 16x16. (R10-proven)
// ---------------------------------------------------------------------------
#define CCHNK 4
template <bool RELU, int KS>
__global__ __launch_bounds__(128, 4) void conv4x4s2_kernel(
    const float* __restrict__ in, const float* __restrict__ w,
    const float* __restrict__ bias, float* __restrict__ out,
    int N, int Cin, int Cout, int Hin, int Win) {
    const int Hout = Hin >> 1, Wout = Win >> 1;
    const int tid = threadIdx.x;
    const int lane4 = tid & 3;
    const int sp = tid >> 2;             // 0..31
    const int sx = sp & 3, sy = sp >> 2; // sx 0..3, sy 0..7
    const int ox0 = blockIdx.x << 4, oy0 = blockIdx.y << 4;
    const int cog = Cout >> 5;
    const int zdiv = cog * KS;
    const int n = blockIdx.z / zdiv;
    const int rem = blockIdx.z % zdiv;
    const int ks = rem / cog;
    const int co0 = (rem % cog) << 5;
    const int CinL = Cin / KS;
    const int ciBase = ks * CinL;
    float* outp = out + (size_t)ks * N * Cout * Hout * Wout;

    __shared__ float s_in[2][CCHNK][34][34];
    __shared__ float s_w[2][CCHNK][16][36];

    u64t acc2[8][4];
#pragma unroll
    for (int p = 0; p < 8; p++)
#pragma unroll
        for (int j = 0; j < 4; j++) acc2[p][j] = 0ull;

    const int iyb = 2 * oy0 - 1, ixb = 2 * ox0 - 1;
    const int by = 4 * sy, bx = 8 * sx;

    for (int idx = tid; idx < 2 * CCHNK * 1156; idx += 128)
        ((float*)s_in)[idx] = 0.f;
    __syncthreads();

    auto load_chunk = [&](int ci0, int buf) {
        const int cc = min(CCHNK, CinL - ci0);
        for (int idx = tid; idx < cc * 1156; idx += 128) {
            int c = idx / 1156, r = idx - c * 1156;
            int yy = r / 34, xx = r - yy * 34;
            int iy = iyb + yy, ix = ixb + xx;
            if ((unsigned)iy < (unsigned)Hin && (unsigned)ix < (unsigned)Win)
                cp_async4(&s_in[buf][c][yy][xx],
                          &in[((n * Cin + ciBase + ci0 + c) * Hin + iy) * Win + ix]);
        }
        const int cseg = cc * 16;
        for (int idx = tid; idx < cc * 512; idx += 128) {
            int co = idx / cseg;
            int r = idx - co * cseg;
            int c = r >> 4, kk = r & 15;
            cp_async4(&s_w[buf][c][kk][co],
                      &w[(co0 + co) * Cin * 16 + (ciBase + ci0) * 16 + r]);
        }
        cp_commit();
    };

    const int nch = (CinL + CCHNK - 1) / CCHNK;
    load_chunk(0, 0);
    for (int it = 0; it < nch; it++) {
        const int buf = it & 1;
        if (it + 1 < nch) { load_chunk((it + 1) * CCHNK, buf ^ 1); cp_wait<1>(); }
        else cp_wait<0>();
        __syncthreads();
        const int cc = min(CCHNK, CinL - it * CCHNK);
        for (int c = 0; c < cc; c++) {
#pragma unroll
            for (int kk = 0; kk < 16; kk++) {
                const int ky = kk >> 2, kx = kk & 3;
                u64t vp[8];
#pragma unroll
                for (int dy = 0; dy < 2; dy++)
#pragma unroll
                    for (int dx = 0; dx < 4; dx++)
                        vp[dy * 4 + dx] = packdup(s_in[buf][c][by + 2 * dy + ky][bx + 2 * dx + kx]);
                const float* wp = &s_w[buf][c][kk][lane4 * 8];
                const ulonglong2 wA = *(const ulonglong2*)(wp);
                const ulonglong2 wB = *(const ulonglong2*)(wp + 4);
                const u64t wv[4] = {wA.x, wA.y, wB.x, wB.y};
#pragma unroll
                for (int j = 0; j < 4; j++)
#pragma unroll
                    for (int p = 0; p < 8; p++)
                        ffma2(acc2[p][j], vp[p], wv[j]);
            }
        }
        __syncthreads();
    }
#pragma unroll
    for (int dy = 0; dy < 2; dy++)
#pragma unroll
        for (int dx = 0; dx < 4; dx++) {
            const int oy = oy0 + 2 * sy + dy, ox = ox0 + 4 * sx + dx;
#pragma unroll
            for (int j = 0; j < 4; j++) {
                const int co = co0 + lane4 * 8 + 2 * j;
                const float2 pv = unpk(acc2[dy * 4 + dx][j]);
                float r0 = pv.x, r1 = pv.y;
                if (KS == 1) { r0 += bias[co]; r1 += bias[co + 1]; }
                if (RELU) { r0 = fmaxf(r0, 0.f); r1 = fmaxf(r1, 0.f); }
                outp[((n * Cout + co) * Hout + oy) * Wout + ox] = r0;
                outp[((n * Cout + co + 1) * Hout + oy) * Wout + ox] = r1;
            }
        }
}

// ---------------------------------------------------------------------------
// convT. 128 threads; 2x4 output pixels x 8 couts. (R10-proven)
// DUAL: dect+upt fusion (two weight/output sets share input tile).
// ---------------------------------------------------------------------------
#define TCHNK 8
template <bool RELU, bool DUAL>
__global__ __launch_bounds__(128, 4) void convT4x4_kernel(
    const float* __restrict__ inA, const float* __restrict__ inB, int CA,
    const float* __restrict__ w, const float* __restrict__ bias,
    float* __restrict__ out,
    const float* __restrict__ w2, const float* __restrict__ bias2,
    float* __restrict__ out2,
    int N, int Cin, int Cout, int Hin, int Win) {
    const int Hout = Hin << 1, Wout = Win << 1;
    const int tid = threadIdx.x;
    const int lane4 = tid & 3;
    const int sp = tid >> 2;
    const int sx = sp & 3, sy = sp >> 2; // sx 0..3, sy 0..7
    const int ox0 = blockIdx.x << 4, oy0 = blockIdx.y << 4;
    const int cog = Cout >> 5;
    const int zdiv = cog * (DUAL ? 2 : 1);
    const int n = blockIdx.z / zdiv;
    int g = blockIdx.z % zdiv;
    const float* wU = w;
    const float* bU = bias;
    float* oU = out;
    if (DUAL && g >= cog) { wU = w2; bU = bias2; oU = out2; g -= cog; }
    const int co0 = g << 5;
    const int CB = Cin - CA;

    __shared__ float s_in[2][TCHNK][10][10];
    __shared__ float s_w[2][TCHNK][16][36];

    u64t acc2[8][4];
#pragma unroll
    for (int p = 0; p < 8; p++)
#pragma unroll
        for (int j = 0; j < 4; j++) acc2[p][j] = 0ull;

    const int iy0 = (oy0 >> 1) - 1, ix0 = (ox0 >> 1) - 1;

    for (int idx = tid; idx < 2 * TCHNK * 100; idx += 128)
        ((float*)s_in)[idx] = 0.f;
    __syncthreads();

    auto load_chunk = [&](int ci0, int buf) {
        const int cc = min(TCHNK, Cin - ci0);
        for (int idx = tid; idx < cc * 100; idx += 128) {
            int c = idx / 100, r = idx - c * 100;
            int yy = r / 10, xx = r - yy * 10;
            int iy = iy0 + yy, ix = ix0 + xx;
            int ci = ci0 + c;
            if ((unsigned)iy < (unsigned)Hin && (unsigned)ix < (unsigned)Win) {
                const float* src = (ci < CA)
                    ? &inA[((n * CA + ci) * Hin + iy) * Win + ix]
                    : &inB[((n * CB + (ci - CA)) * Hin + iy) * Win + ix];
                cp_async4(&s_in[buf][c][yy][xx], src);
            }
        }
        for (int idx = tid; idx < cc * 512; idx += 128) {
            int c = idx >> 9, r = idx & 511; // r = co*16 + kk
            int co = r >> 4, kk = r & 15;
            cp_async4(&s_w[buf][c][kk][co], &wU[(ci0 + c) * Cout * 16 + co0 * 16 + r]);
        }
        cp_commit();
    };

    const int nch = (Cin + TCHNK - 1) / TCHNK;
    load_chunk(0, 0);
    for (int it = 0; it < nch; it++) {
        const int buf = it & 1;
        if (it + 1 < nch) { load_chunk((it + 1) * TCHNK, buf ^ 1); cp_wait<1>(); }
        else cp_wait<0>();
        __syncthreads();
        const int cc = min(TCHNK, Cin - it * TCHNK);
        for (int c = 0; c < cc; c++) {
            // register tile: rows sy..sy+2, cols 2sx..2sx+3
            u64t vin[3][4];
#pragma unroll
            for (int i = 0; i < 3; i++)
#pragma unroll
                for (int j2 = 0; j2 < 4; j2++)
                    vin[i][j2] = packdup(s_in[buf][c][sy + i][2 * sx + j2]);
#pragma unroll
            for (int kk = 0; kk < 16; kk++) {
                const int ky = kk >> 2, kx = kk & 3;
                const int dy = (ky & 1) ? 0 : 1;
                const int ry = (ky & 1) ? (1 - ((ky - 1) >> 1)) : (2 - (ky >> 1));
                const int dxx0 = (kx & 1) ? 0 : 1;          // first matching out-col offset
                const int c0 = ((dxx0 + 1 - kx) >> 1) + 1;  // vin col for dxx0 (0..2)
                const u64t va = vin[ry][c0];
                const u64t vb = vin[ry][c0 + 1];            // for dxx0 + 2
                const float* wp = &s_w[buf][c][kk][lane4 * 8];
                const ulonglong2 wA = *(const ulonglong2*)(wp);
                const ulonglong2 wB = *(const ulonglong2*)(wp + 4);
                const u64t wv[4] = {wA.x, wA.y, wB.x, wB.y};
                u64t* aa = acc2[dy * 4 + dxx0];
                u64t* ab = acc2[dy * 4 + dxx0 + 2];
#pragma unroll
                for (int j = 0; j < 4; j++) {
                    ffma2(aa[j], va, wv[j]);
                    ffma2(ab[j], vb, wv[j]);
                }
            }
        }
        __syncthreads();
    }
#pragma unroll
    for (int dy = 0; dy < 2; dy++)
#pragma unroll
        for (int dx = 0; dx < 4; dx++) {
            const int oy = oy0 + 2 * sy + dy, ox = ox0 + 4 * sx + dx;
#pragma unroll
            for (int j = 0; j < 4; j++) {
                const int co = co0 + lane4 * 8 + 2 * j;
                const float2 pv = unpk(acc2[dy * 4 + dx][j]);
                float r0 = pv.x + bU[co];
                float r1 = pv.y + bU[co + 1];
                if (RELU) { r0 = fmaxf(r0, 0.f); r1 = fmaxf(r1, 0.f); }
                oU[((n * Cout + co) * Hout + oy) * Wout + ox] = r0;
                oU[((n * Cout + co + 1) * Hout + oy) * Wout + ox] = r1;
            }
        }
}

// ---------------------------------------------------------------------------
// ConvT small (Cout=3), cp.async double-buffered (proven version)
// ---------------------------------------------------------------------------
#define SCHNK 8
__global__ __launch_bounds__(256) void convT4x4_small_kernel(
    const float* __restrict__ in, const float* __restrict__ w,
    const float* __restrict__ bias, float* __restrict__ out,
    int N, int Cin, int Hin, int Win) {
    const int Hout = Hin << 1, Wout = Win << 1;
    const int tid = threadIdx.x;
    const int sx = tid & 15, sy = tid >> 4;
    const int ox0 = blockIdx.x << 5, oy0 = blockIdx.y << 5;
    const int n = blockIdx.z;

    __shared__ float s_in[2][SCHNK][18][18];
    __shared__ float s_w[2][SCHNK][16][4];

    u64t acc01[4];
    float acc2s[4];
#pragma unroll
    for (int p = 0; p < 4; p++) { acc01[p] = 0ull; acc2s[p] = 0.f; }

    const int iy0 = (oy0 >> 1) - 1, ix0 = (ox0 >> 1) - 1;

    for (int idx = tid; idx < 2 * SCHNK * 324; idx += 256)
        ((float*)s_in)[idx] = 0.f;
    __syncthreads();

    auto load_chunk = [&](int ci0, int buf) {
        const int cc = min(SCHNK, Cin - ci0);
        for (int idx = tid; idx < cc * 324; idx += 256) {
            int c = idx / 324, r = idx - c * 324;
            int yy = r / 18, xx = r - yy * 18;
            int iy = iy0 + yy, ix = ix0 + xx;
            if ((unsigned)iy < (unsigned)Hin && (unsigned)ix < (unsigned)Win)
                cp_async4(&s_in[buf][c][yy][xx],
                          &in[((n * Cin + ci0 + c) * Hin + iy) * Win + ix]);
        }
        for (int idx = tid; idx < cc * 48; idx += 256) {
            int c = idx / 48, r = idx - c * 48;
            int co = r >> 4, kk = r & 15;
            cp_async4(&s_w[buf][c][kk][co], &w[(ci0 + c) * 3 * 16 + r]);
        }
        cp_commit();
    };

    const int nch = (Cin + SCHNK - 1) / SCHNK;
    load_chunk(0, 0);
    for (int it = 0; it < nch; it++) {
        const int buf = it & 1;
        if (it + 1 < nch) { load_chunk((it + 1) * SCHNK, buf ^ 1); cp_wait<1>(); }
        else cp_wait<0>();
        __syncthreads();
        const int cc = min(SCHNK, Cin - it * SCHNK);
        for (int c = 0; c < cc; c++) {
            float vin[3][3];
#pragma unroll
            for (int i = 0; i < 3; i++)
#pragma unroll
                for (int j2 = 0; j2 < 3; j2++) vin[i][j2] = s_in[buf][c][sy + i][sx + j2];
#pragma unroll
            for (int kk = 0; kk < 16; kk++) {
                const int ky = kk >> 2, kx = kk & 3;
                const int dy = (ky & 1) ? 0 : 1;
                const int ry = (ky & 1) ? (1 - ((ky - 1) >> 1)) : (2 - (ky >> 1));
                const int dx = (kx & 1) ? 0 : 1;
                const int rx = (kx & 1) ? (1 - ((kx - 1) >> 1)) : (2 - (kx >> 1));
                const float vs = vin[ry][rx];
                const u64t v = packdup(vs);
                const u64t w01 = *(const u64t*)&s_w[buf][c][kk][0];
                const int p = dy * 2 + dx;
                ffma2(acc01[p], v, w01);
                acc2s[p] = fmaf(vs, s_w[buf][c][kk][2], acc2s[p]);
            }
        }
        __syncthreads();
    }
#pragma unroll
    for (int dy = 0; dy < 2; dy++)
#pragma unroll
        for (int dx = 0; dx < 2; dx++) {
            const int oy = oy0 + 2 * sy + dy, ox = ox0 + 2 * sx + dx;
            const float2 pv = unpk(acc01[dy * 2 + dx]);
            out[((n * 3 + 0) * Hout + oy) * Wout + ox] = pv.x + bias[0];
            out[((n * 3 + 1) * Hout + oy) * Wout + ox] = pv.y + bias[1];
            out[((n * 3 + 2) * Hout + oy) * Wout + ox] = acc2s[dy * 2 + dx] + bias[2];
        }
}

// ---------------------------------------------------------------------------
// Fused 1x1 conv + VQ. 128 threads/block, 64-wide codebook chunks.
// MODE 0: concat input. MODE 1: relu(sum of 4 split-K partials + cbias).
// ---------------------------------------------------------------------------
template <int MODE>
__global__ __launch_bounds__(128) void conv1x1_quantize_kernel(
    const float* __restrict__ inA, const float* __restrict__ inB, int CA, int CB,
    const float* __restrict__ cbias,
    const float* __restrict__ w, const float* __restrict__ b,
    const float* __restrict__ embed, const float* __restrict__ norms,
    float* __restrict__ qout, float* __restrict__ idout, float* __restrict__ acc,
    int HW) {
    const int tid = threadIdx.x;
    const int v = blockIdx.x * 128 + tid;
    const int n = v / HW, hw = v - n * HW;
    const int Cin = (MODE == 0) ? (CA + CB) : CA;

    __shared__ float s_w[2][16][68];
    __shared__ float s_e[2][64][68];
    __shared__ float s_n[2][64];

    u64t f2[32];
#pragma unroll
    for (int i = 0; i < 32; i++) f2[i] = 0ull;

    auto load_w = [&](int ci0, int buf) {
        for (int idx = tid; idx < 1024; idx += 128) {
            int c = idx & 15, co = idx >> 4;
            cp_async4(&s_w[buf][c][co], &w[co * Cin + ci0 + c]);
        }
        cp_commit();
    };

    const int nch = Cin >> 4;
    load_w(0, 0);
    for (int it = 0; it < nch; it++) {
        const int buf = it & 1;
        if (it + 1 < nch) { load_w((it + 1) * 16, buf ^ 1); cp_wait<1>(); }
        else cp_wait<0>();
        __syncthreads();
        const int ci0 = it * 16;
#pragma unroll 4
        for (int c = 0; c < 16; c++) {
            const int ci = ci0 + c;
            float val;
            if (MODE == 0) {
                if (ci < CA)
                    val = inA[(n * CA + ci) * HW + hw];
                else
                    val = inB[(n * CB + (ci - CA)) * HW + hw];
            } else {
                const int off = (n * CA + ci) * HW + hw;
                val = fmaxf(((inA[off] + inA[off + ENCT_STRIDE]) +
                             (inA[off + 2 * ENCT_STRIDE] + inA[off + 3 * ENCT_STRIDE])) +
                            __ldg(&cbias[ci]), 0.f);
            }
            const u64t vp = packdup(val);
            const ulonglong2* wr = (const ulonglong2*)s_w[buf][c];
#pragma unroll
            for (int j = 0; j < 16; j++) {
                const ulonglong2 wv = wr[j];
                ffma2(f2[2 * j + 0], vp, wv.x);
                ffma2(f2[2 * j + 1], vp, wv.y);
            }
        }
        __syncthreads();
    }
    // bias
    float f[64];
#pragma unroll
    for (int i = 0; i < 32; i++) {
        const float2 pv = unpk(f2[i]);
        f[2 * i] = pv.x + b[2 * i];
        f[2 * i + 1] = pv.y + b[2 * i + 1];
        f2[i] = pack2(f[2 * i], f[2 * i + 1]);
    }

    auto load_e = [&](int k0, int buf) {
        for (int idx = tid; idx < 4096; idx += 128) {
            int d = idx >> 6, k = idx & 63;
            cp_async4(&s_e[buf][k][d], &embed[d * 512 + k0 + k]);
        }
        if (tid < 64) cp_async4(&s_n[buf][tid], &norms[k0 + tid]);
        cp_commit();
    };

    float best = 3.4e38f;
    int bid = 0;
    load_e(0, 0);
    for (int it = 0; it < 8; it++) {
        const int buf = it & 1;
        if (it + 1 < 8) { load_e((it + 1) * 64, buf ^ 1); cp_wait<1>(); }
        else cp_wait<0>();
        __syncthreads();
        const int k0 = it * 64;
        for (int k = 0; k < 64; k++) {
            u64t d0 = 0ull, d1 = 0ull;
            const ulonglong2* er = (const ulonglong2*)s_e[buf][k];
#pragma unroll
            for (int j = 0; j < 16; j++) {
                const ulonglong2 e = er[j];
                ffma2(d0, f2[2 * j + 0], e.x);
                ffma2(d1, f2[2 * j + 1], e.y);
            }
            const float2 a0 = unpk(d0), a1 = unpk(d1);
            const float sc = s_n[buf][k] - 2.f * ((a0.x + a0.y) + (a1.x + a1.y));
            if (sc < best) { best = sc; bid = k0 + k; }
        }
        __syncthreads();
    }

    float lsum = 0.f;
#pragma unroll
    for (int d = 0; d < 64; d++) {
        const float q = __ldg(&embed[d * 512 + bid]);
        const float df = q - f[d];
        lsum = fmaf(df, df, lsum);
        qout[(n * 64 + d) * HW + hw] = q;
    }
    idout[v] = (float)bid;
#pragma unroll
    for (int o = 16; o > 0; o >>= 1) lsum += __shfl_down_sync(0xffffffffu, lsum, o);
    if ((tid & 31) == 0) atomicAdd(acc, lsum);
}

__global__ void finalize_loss_kernel(const float* __restrict__ acc, float* __restrict__ o) {
    o[0] = acc[0] * (1.f / 1048576.f) + acc[1] * (1.f / 4194304.f);
}

extern "C" void kernel_launch(void* const* d_in, const int* in_sizes, int n_in,
                              void* d_out, int out_size) {
    (void)in_sizes; (void)n_in; (void)out_size;
    const float* x       = (const float*)d_in[0];
    const float* wb1     = (const float*)d_in[1];
    const float* bb1     = (const float*)d_in[2];
    const float* wb2     = (const float*)d_in[3];
    const float* bb2     = (const float*)d_in[4];
    const float* wt1     = (const float*)d_in[5];
    const float* bt1     = (const float*)d_in[6];
    const float* wqt     = (const float*)d_in[7];
    const float* bqt     = (const float*)d_in[8];
    const float* embed_t = (const float*)d_in[9];
    const float* wdt     = (const float*)d_in[10];
    const float* bdt     = (const float*)d_in[11];
    const float* wqb     = (const float*)d_in[12];
    const float* bqb     = (const float*)d_in[13];
    const float* embed_b = (const float*)d_in[14];
    const float* wup     = (const float*)d_in[15];
    const float* bup     = (const float*)d_in[16];
    const float* wd1     = (const float*)d_in[17];
    const float* bd1     = (const float*)d_in[18];
    const float* wd2     = (const float*)d_in[19];
    const float* bd2     = (const float*)d_in[20];

    float* out    = (float*)d_out;
    float* o_xhat = out;
    float* o_qt   = out + 3145728;
    float* o_qb   = out + 4194304;
    float* o_loss = out + 8388608;
    float* o_idt  = out + 8388609;
    float* o_idb  = out + 8404993;

    float *encb1, *encb, *enct, *dect, *upt, *h, *normt, *normb, *acc;
    cudaGetSymbolAddress((void**)&encb1, g_encb1);
    cudaGetSymbolAddress((void**)&encb,  g_encb);
    cudaGetSymbolAddress((void**)&enct,  g_enct);
    cudaGetSymbolAddress((void**)&dect,  g_dect);
    cudaGetSymbolAddress((void**)&upt,   g_upt);
    cudaGetSymbolAddress((void**)&h,     g_h);
    cudaGetSymbolAddress((void**)&normt, g_normt);
    cudaGetSymbolAddress((void**)&normb, g_normb);
    cudaGetSymbolAddress((void**)&acc,   g_acc);

    init_kernel<<<1, 512>>>(embed_t, embed_b, normt, normb, acc);

    // ---- encoder ----
    conv4x4s2_kernel<true, 1><<<dim3(8, 8, 16 * 4), 128>>>(x, wb1, bb1, encb1, 16, 3, 128, 256, 256);
    conv4x4s2_kernel<true, 1><<<dim3(4, 4, 16 * 4), 128>>>(encb1, wb2, bb2, encb, 16, 128, 128, 128, 128);
    // conv3: split-K x4 -> partials; bias+relu fused into quant_t input
    conv4x4s2_kernel<false, 4><<<dim3(2, 2, 16 * 4 * 4), 128>>>(encb, wt1, nullptr, enct, 16, 128, 128, 64, 64);

    // ---- top quantize (reads relu(p0+p1+p2+p3+bt1)) ----
    conv1x1_quantize_kernel<1><<<16384 / 128, 128>>>(enct, nullptr, 128, 0, bt1,
                                                     wqt, bqt, embed_t, normt, o_qt, o_idt, acc + 0, 1024);

    // ---- decoder_top + upsample_t fused (both read quant_t) ----
    convT4x4_kernel<false, true><<<dim3(4, 4, 16 * 4), 128>>>(
        o_qt, o_qt, 64, wdt, bdt, dect, wup, bup, upt, 16, 64, 64, 32, 32);

    // ---- bottom quantize ----
    conv1x1_quantize_kernel<0><<<65536 / 128, 128>>>(dect, encb, 64, 128, nullptr,
                                                     wqb, bqb, embed_b, normb, o_qb, o_idb, acc + 1, 4096);

    // ---- decode ----
    convT4x4_kernel<true, false><<<dim3(8, 8, 16 * 2), 128>>>(
        upt, o_qb, 64, wd1, bd1, h, nullptr, nullptr, nullptr, 16, 128, 64, 64, 64);
    convT4x4_small_kernel<<<dim3(8, 8, 16), 256>>>(h, wd2, bd2, o_xhat, 16, 64, 128, 128);

    finalize_loss_kernel<<<1, 1>>>(acc, o_loss);
}